// round 6
// baseline (speedup 1.0000x reference)
#include <cuda_runtime.h>

// LIF recurrence, B=64 T=256 U=1024 fp32.
// Time-segmented x8: T split into 8 segments of 32; each thread warms up 16
// steps from v=0 (tau=0.25 => carried-state error ~2e-10, below fp32 ulp).
// 262144 threads (~48-56 warps/SM) to break the latency bound.
// D=4 ping-pong pipeline; regs capped for 12 blocks/SM.

#define T_LEN 256
#define U2    512             // U/2 float2 lanes
#define SEG   32
#define W     16
#define NSEG  (T_LEN / SEG)   // 8
#define D     4               // t-steps per chunk
#define NWCH  (W / D)         // 4 warmup chunks
#define NCH   (NWCH + SEG / D) // 12 chunks total

__global__ __launch_bounds__(128, 12)
void lif_kernel(const float2* __restrict__ in, float2* __restrict__ out) {
    const int gid = blockIdx.x * blockDim.x + threadIdx.x;   // 0..262143
    const int u2  = gid & (U2 - 1);
    const int rs  = gid >> 9;
    const int seg = rs & (NSEG - 1);
    const int b   = rs >> 3;

    const float2* __restrict__ ip = in  + (size_t)b * T_LEN * U2 + u2;
    float2*       __restrict__ op = out + (size_t)b * T_LEN * U2 + u2;

    const int t0 = seg * SEG;
    const int ts = (seg == 0) ? 0 : (t0 - W);   // warmup start (seg0's warmup discarded)

    float vx = 0.f, vy = 0.f;
    float2 A[D], B[D];

    // chunk k start time: warmup chunks from ts, main chunks from t0
    #define CH_T(k) (((k) < NWCH) ? (ts + (k) * D) : (t0 + ((k) - NWCH) * D))

    #define LOADCH(buf, tstart) do {                                   \
        _Pragma("unroll")                                              \
        for (int i = 0; i < D; ++i)                                    \
            (buf)[i] = ip[(size_t)((tstart) + i) * U2];                \
    } while (0)

    #define PROCCH(buf, k) do {                                        \
        _Pragma("unroll")                                              \
        for (int i = 0; i < D; ++i) {                                  \
            float2 x = (buf)[i];                                       \
            vx = fmaf(0.25f, vx, 0.75f * x.x);                         \
            vy = fmaf(0.25f, vy, 0.75f * x.y);                         \
            float sx = (vx > 1.0f) ? 1.0f : 0.0f;                      \
            float sy = (vy > 1.0f) ? 1.0f : 0.0f;                      \
            vx -= sx; vy -= sy;                                        \
            if ((k) >= NWCH)                                           \
                __stcs(&op[(size_t)(CH_T(k) + i) * U2],                \
                       make_float2(sx, sy));                           \
        }                                                              \
        if ((k) == NWCH - 1 && seg == 0) { vx = 0.f; vy = 0.f; }       \
    } while (0)

    // prime ping-pong
    LOADCH(A, CH_T(0));
    LOADCH(B, CH_T(1));

    #pragma unroll
    for (int k = 0; k < NCH; k += 2) {
        PROCCH(A, k);
        if (k + 2 < NCH) LOADCH(A, CH_T(k + 2));
        if (k + 1 < NCH) PROCCH(B, k + 1);
        if (k + 3 < NCH) LOADCH(B, CH_T(k + 3));
    }

    #undef CH_T
    #undef LOADCH
    #undef PROCCH
}

extern "C" void kernel_launch(void* const* d_in, const int* in_sizes, int n_in,
                              void* d_out, int out_size) {
    const float2* in  = (const float2*)d_in[0];
    float2*       out = (float2*)d_out;

    const int total   = in_sizes[0];                 // B*T*U
    const int lanes   = total / 2 / T_LEN;           // B*U2 = 32768
    const int threads = lanes * NSEG;                // 262144

    const int block = 128;
    const int grid  = threads / block;               // 2048
    lif_kernel<<<grid, block>>>(in, out);
}